// round 2
// baseline (speedup 1.0000x reference)
#include <cuda_runtime.h>
#include <cuda_bf16.h>
#include <math.h>

// Problem dims (fixed)
#define BATCH 32
#define SEQ   2048
#define VLEN  1024
#define HID   1024
#define MROWS (BATCH * SEQ)   // 65536

// scratch (no cudaMalloc allowed)
__device__ float g_e[MROWS];
__device__ float g_beta[MROWS];
__device__ float g_hproj[BATCH * HID];

// ---------------------------------------------------------------------------
// Kernel 0: zero e and out
// ---------------------------------------------------------------------------
__global__ void zero_kernel(float* __restrict__ e, float* __restrict__ out) {
    int i = blockIdx.x * blockDim.x + threadIdx.x;
    if (i < MROWS) e[i] = 0.0f;
    if (i < BATCH * VLEN) out[i] = 0.0f;
}

// ---------------------------------------------------------------------------
// Kernel 1: h_proj[b,d] = sum_k h[b,k]*W_w[d,k] + W_b[d]
// warp per d; W_w read coalesced exactly once; h hits L2.
// ---------------------------------------------------------------------------
__global__ void hproj_kernel(const float* __restrict__ h,
                             const float* __restrict__ Ww,
                             const float* __restrict__ Wb,
                             float* __restrict__ hproj) {
    int gwarp = (blockIdx.x * blockDim.x + threadIdx.x) >> 5;
    int lane  = threadIdx.x & 31;
    if (gwarp >= HID) return;
    int d = gwarp;

    float wreg[32];
#pragma unroll
    for (int i = 0; i < 32; i++) wreg[i] = Ww[(size_t)d * HID + i * 32 + lane];
    float bias = Wb[d];

    for (int b = 0; b < BATCH; b++) {
        const float* hb = h + (size_t)b * HID;
        float acc = 0.0f;
#pragma unroll
        for (int i = 0; i < 32; i++) acc = fmaf(wreg[i], hb[i * 32 + lane], acc);
#pragma unroll
        for (int off = 16; off > 0; off >>= 1)
            acc += __shfl_down_sync(0xffffffffu, acc, off);
        if (lane == 0) hproj[b * HID + d] = acc + bias;
    }
}

// ---------------------------------------------------------------------------
// Kernel 2: fused GEMM + tanh-dot epilogue.
//   C[r,d] = sum_v V[r,v] * U_w[d,v]   (K fully reduced inside CTA)
//   e[r] += sum_d w_w[d] * tanh(hproj[b,d] + C[r,d])   (atomicAdd partials)
// 128x128x8 tiling, 256 threads, 8x8 per thread.
// ---------------------------------------------------------------------------
#define BM 128
#define BN 128
#define BK 8
#define TM 8
#define TN 8

__global__ __launch_bounds__(256, 2)
void gemm_tanh_e_kernel(const float* __restrict__ V,
                        const float* __restrict__ U,
                        const float* __restrict__ hproj,
                        const float* __restrict__ ww,
                        float* __restrict__ e) {
    __shared__ float As[BK][BM];
    __shared__ float Bs[BK][BN];
    __shared__ float hp_s[BN];
    __shared__ float ww_s[BN];

    const int tid  = threadIdx.x;
    const int row0 = blockIdx.y * BM;        // global row (b*S+s) offset
    const int col0 = blockIdx.x * BN;        // d offset
    const int b    = row0 >> 11;             // SEQ = 2048, tile fits in one b

    if (tid < BN) {
        hp_s[tid] = hproj[b * HID + col0 + tid];
        ww_s[tid] = ww[col0 + tid];
    }

    const int tx = tid & 15;                 // 16 cols of threads
    const int ty = tid >> 4;                 // 16 rows of threads

    // A tile loads: 128x8 = 1024 floats = 256 threads * float4
    const int aRow = tid >> 1;
    const int aCol = (tid & 1) * 4;
    const float* Aptr = V + (size_t)row0 * VLEN;
    const float* Bptr = U + (size_t)col0 * VLEN;

    float acc[TM][TN];
#pragma unroll
    for (int i = 0; i < TM; i++)
#pragma unroll
        for (int j = 0; j < TN; j++) acc[i][j] = 0.0f;

    for (int k0 = 0; k0 < VLEN; k0 += BK) {
        float4 a4 = *(const float4*)(Aptr + (size_t)aRow * VLEN + k0 + aCol);
        As[aCol + 0][aRow] = a4.x;
        As[aCol + 1][aRow] = a4.y;
        As[aCol + 2][aRow] = a4.z;
        As[aCol + 3][aRow] = a4.w;
        float4 b4 = *(const float4*)(Bptr + (size_t)aRow * VLEN + k0 + aCol);
        Bs[aCol + 0][aRow] = b4.x;
        Bs[aCol + 1][aRow] = b4.y;
        Bs[aCol + 2][aRow] = b4.z;
        Bs[aCol + 3][aRow] = b4.w;
        __syncthreads();

#pragma unroll
        for (int k = 0; k < BK; k++) {
            float ra[TM], rb[TN];
            float4 t0 = *(const float4*)&As[k][ty * TM];
            float4 t1 = *(const float4*)&As[k][ty * TM + 4];
            ra[0]=t0.x; ra[1]=t0.y; ra[2]=t0.z; ra[3]=t0.w;
            ra[4]=t1.x; ra[5]=t1.y; ra[6]=t1.z; ra[7]=t1.w;
            float4 u0 = *(const float4*)&Bs[k][tx * TN];
            float4 u1 = *(const float4*)&Bs[k][tx * TN + 4];
            rb[0]=u0.x; rb[1]=u0.y; rb[2]=u0.z; rb[3]=u0.w;
            rb[4]=u1.x; rb[5]=u1.y; rb[6]=u1.z; rb[7]=u1.w;
#pragma unroll
            for (int i = 0; i < TM; i++)
#pragma unroll
                for (int j = 0; j < TN; j++)
                    acc[i][j] = fmaf(ra[i], rb[j], acc[i][j]);
        }
        __syncthreads();
    }

    // epilogue: e partial = sum_d ww[d]*tanh(hp[d] + C)
#pragma unroll
    for (int i = 0; i < TM; i++) {
        float es = 0.0f;
#pragma unroll
        for (int j = 0; j < TN; j++) {
            int dl = tx * TN + j;
            es += ww_s[dl] * tanhf(hp_s[dl] + acc[i][j]);
        }
        // reduce across the 16 threads sharing this row (same ty)
#pragma unroll
        for (int off = 8; off > 0; off >>= 1)
            es += __shfl_down_sync(0xffffffffu, es, off, 16);
        if (tx == 0) atomicAdd(&e[row0 + ty * TM + i], es);
    }
}

// ---------------------------------------------------------------------------
// Kernel 3: softmax over s for each b (32 blocks)
// ---------------------------------------------------------------------------
__global__ void softmax_kernel(const float* __restrict__ e,
                               float* __restrict__ beta) {
    __shared__ float red[256];
    int b = blockIdx.x;
    int tid = threadIdx.x;
    const float* eb = e + (size_t)b * SEQ;

    float m = -1e30f;
    for (int i = tid; i < SEQ; i += 256) m = fmaxf(m, eb[i]);
    red[tid] = m;
    __syncthreads();
    for (int s = 128; s > 0; s >>= 1) {
        if (tid < s) red[tid] = fmaxf(red[tid], red[tid + s]);
        __syncthreads();
    }
    m = red[0];
    __syncthreads();

    float sum = 0.0f;
    for (int i = tid; i < SEQ; i += 256) sum += expf(eb[i] - m);
    red[tid] = sum;
    __syncthreads();
    for (int s = 128; s > 0; s >>= 1) {
        if (tid < s) red[tid] += red[tid + s];
        __syncthreads();
    }
    float inv = 1.0f / red[0];

    for (int i = tid; i < SEQ; i += 256)
        beta[(size_t)b * SEQ + i] = expf(eb[i] - m) * inv;
}

// ---------------------------------------------------------------------------
// Kernel 4: out[b,v] = sum_s beta[b,s]*V[b,s,v]; s split across 8 CTAs per b.
// ---------------------------------------------------------------------------
#define SCHUNK 256
__global__ void out_kernel(const float* __restrict__ V,
                           const float* __restrict__ beta,
                           float* __restrict__ out) {
    __shared__ float bs[SCHUNK];
    int b  = blockIdx.y;
    int sc = blockIdx.x;               // 8 chunks of 256
    int tid = threadIdx.x;             // 256 threads, 4 v each (float4)

    bs[tid] = beta[(size_t)b * SEQ + sc * SCHUNK + tid];
    __syncthreads();

    const float4* Vp = (const float4*)(V + (size_t)b * SEQ * VLEN
                                         + (size_t)sc * SCHUNK * VLEN) + tid;
    float4 acc = make_float4(0.f, 0.f, 0.f, 0.f);
#pragma unroll 4
    for (int s = 0; s < SCHUNK; s++) {
        float4 v = Vp[(size_t)s * (VLEN / 4)];
        float w = bs[s];
        acc.x = fmaf(w, v.x, acc.x);
        acc.y = fmaf(w, v.y, acc.y);
        acc.z = fmaf(w, v.z, acc.z);
        acc.w = fmaf(w, v.w, acc.w);
    }
    float* o = out + (size_t)b * VLEN + tid * 4;
    atomicAdd(o + 0, acc.x);
    atomicAdd(o + 1, acc.y);
    atomicAdd(o + 2, acc.z);
    atomicAdd(o + 3, acc.w);
}

// ---------------------------------------------------------------------------
extern "C" void kernel_launch(void* const* d_in, const int* in_sizes, int n_in,
                              void* d_out, int out_size) {
    const float* h   = (const float*)d_in[0];
    const float* V   = (const float*)d_in[1];
    const float* Ww  = (const float*)d_in[2];
    const float* Wb  = (const float*)d_in[3];
    const float* Uw  = (const float*)d_in[4];
    const float* ww  = (const float*)d_in[5];
    float* out = (float*)d_out;

    float* e; float* beta; float* hproj;
    cudaGetSymbolAddress((void**)&e, g_e);
    cudaGetSymbolAddress((void**)&beta, g_beta);
    cudaGetSymbolAddress((void**)&hproj, g_hproj);

    zero_kernel<<<(MROWS + 255) / 256, 256>>>(e, out);
    hproj_kernel<<<(HID * 32 + 255) / 256, 256>>>(h, Ww, Wb, hproj);
    {
        dim3 grid(HID / BN, MROWS / BM);   // (8, 512)
        gemm_tanh_e_kernel<<<grid, 256>>>(V, Uw, hproj, ww, e);
    }
    softmax_kernel<<<BATCH, 256>>>(e, beta);
    {
        dim3 grid(SEQ / SCHUNK, BATCH);    // (8, 32)
        out_kernel<<<grid, SCHUNK>>>(V, beta, out);
    }
}

// round 3
// speedup vs baseline: 1.0002x; 1.0002x over previous
#include <cuda_runtime.h>
#include <cuda_bf16.h>
#include <math.h>

// Problem dims (fixed)
#define BATCH 32
#define SEQ   2048
#define VLEN  1024
#define HID   1024
#define MROWS (BATCH * SEQ)   // 65536

// scratch (no cudaMalloc allowed)
__device__ float g_e[MROWS];
__device__ float g_beta[MROWS];
__device__ float g_hproj[BATCH * HID];

// ---------------------------------------------------------------------------
// Kernel 0: zero e and out
// ---------------------------------------------------------------------------
__global__ void zero_kernel(float* __restrict__ e, float* __restrict__ out) {
    int i = blockIdx.x * blockDim.x + threadIdx.x;
    if (i < MROWS) e[i] = 0.0f;
    if (i < BATCH * VLEN) out[i] = 0.0f;
}

// ---------------------------------------------------------------------------
// Kernel 1: h_proj[b,d] = sum_k h[b,k]*W_w[d,k] + W_b[d]
// warp per d; W_w read coalesced exactly once; h hits L2.
// ---------------------------------------------------------------------------
__global__ void hproj_kernel(const float* __restrict__ h,
                             const float* __restrict__ Ww,
                             const float* __restrict__ Wb,
                             float* __restrict__ hproj) {
    int gwarp = (blockIdx.x * blockDim.x + threadIdx.x) >> 5;
    int lane  = threadIdx.x & 31;
    if (gwarp >= HID) return;
    int d = gwarp;

    float wreg[32];
#pragma unroll
    for (int i = 0; i < 32; i++) wreg[i] = Ww[(size_t)d * HID + i * 32 + lane];
    float bias = Wb[d];

    for (int b = 0; b < BATCH; b++) {
        const float* hb = h + (size_t)b * HID;
        float acc = 0.0f;
#pragma unroll
        for (int i = 0; i < 32; i++) acc = fmaf(wreg[i], hb[i * 32 + lane], acc);
#pragma unroll
        for (int off = 16; off > 0; off >>= 1)
            acc += __shfl_down_sync(0xffffffffu, acc, off);
        if (lane == 0) hproj[b * HID + d] = acc + bias;
    }
}

// ---------------------------------------------------------------------------
// Kernel 2: fused GEMM + tanh-dot epilogue.
//   C[r,d] = sum_v V[r,v] * U_w[d,v]   (K fully reduced inside CTA)
//   e[r] += sum_d w_w[d] * tanh(hproj[b,d] + C[r,d])   (atomicAdd partials)
// 128x128x8 tiling, 256 threads, 8x8 per thread.
// ---------------------------------------------------------------------------
#define BM 128
#define BN 128
#define BK 8
#define TM 8
#define TN 8

__global__ __launch_bounds__(256, 2)
void gemm_tanh_e_kernel(const float* __restrict__ V,
                        const float* __restrict__ U,
                        const float* __restrict__ hproj,
                        const float* __restrict__ ww,
                        float* __restrict__ e) {
    __shared__ float As[BK][BM];
    __shared__ float Bs[BK][BN];
    __shared__ float hp_s[BN];
    __shared__ float ww_s[BN];

    const int tid  = threadIdx.x;
    const int row0 = blockIdx.y * BM;        // global row (b*S+s) offset
    const int col0 = blockIdx.x * BN;        // d offset
    const int b    = row0 >> 11;             // SEQ = 2048, tile fits in one b

    if (tid < BN) {
        hp_s[tid] = hproj[b * HID + col0 + tid];
        ww_s[tid] = ww[col0 + tid];
    }

    const int tx = tid & 15;                 // 16 cols of threads
    const int ty = tid >> 4;                 // 16 rows of threads

    // A tile loads: 128x8 = 1024 floats = 256 threads * float4
    const int aRow = tid >> 1;
    const int aCol = (tid & 1) * 4;
    const float* Aptr = V + (size_t)row0 * VLEN;
    const float* Bptr = U + (size_t)col0 * VLEN;

    float acc[TM][TN];
#pragma unroll
    for (int i = 0; i < TM; i++)
#pragma unroll
        for (int j = 0; j < TN; j++) acc[i][j] = 0.0f;

    for (int k0 = 0; k0 < VLEN; k0 += BK) {
        float4 a4 = *(const float4*)(Aptr + (size_t)aRow * VLEN + k0 + aCol);
        As[aCol + 0][aRow] = a4.x;
        As[aCol + 1][aRow] = a4.y;
        As[aCol + 2][aRow] = a4.z;
        As[aCol + 3][aRow] = a4.w;
        float4 b4 = *(const float4*)(Bptr + (size_t)aRow * VLEN + k0 + aCol);
        Bs[aCol + 0][aRow] = b4.x;
        Bs[aCol + 1][aRow] = b4.y;
        Bs[aCol + 2][aRow] = b4.z;
        Bs[aCol + 3][aRow] = b4.w;
        __syncthreads();

#pragma unroll
        for (int k = 0; k < BK; k++) {
            float ra[TM], rb[TN];
            float4 t0 = *(const float4*)&As[k][ty * TM];
            float4 t1 = *(const float4*)&As[k][ty * TM + 4];
            ra[0]=t0.x; ra[1]=t0.y; ra[2]=t0.z; ra[3]=t0.w;
            ra[4]=t1.x; ra[5]=t1.y; ra[6]=t1.z; ra[7]=t1.w;
            float4 u0 = *(const float4*)&Bs[k][tx * TN];
            float4 u1 = *(const float4*)&Bs[k][tx * TN + 4];
            rb[0]=u0.x; rb[1]=u0.y; rb[2]=u0.z; rb[3]=u0.w;
            rb[4]=u1.x; rb[5]=u1.y; rb[6]=u1.z; rb[7]=u1.w;
#pragma unroll
            for (int i = 0; i < TM; i++)
#pragma unroll
                for (int j = 0; j < TN; j++)
                    acc[i][j] = fmaf(ra[i], rb[j], acc[i][j]);
        }
        __syncthreads();
    }

    // epilogue: e partial = sum_d ww[d]*tanh(hp[d] + C)
#pragma unroll
    for (int i = 0; i < TM; i++) {
        float es = 0.0f;
#pragma unroll
        for (int j = 0; j < TN; j++) {
            int dl = tx * TN + j;
            es += ww_s[dl] * tanhf(hp_s[dl] + acc[i][j]);
        }
        // reduce across the 16 threads sharing this row (same ty)
#pragma unroll
        for (int off = 8; off > 0; off >>= 1)
            es += __shfl_down_sync(0xffffffffu, es, off, 16);
        if (tx == 0) atomicAdd(&e[row0 + ty * TM + i], es);
    }
}

// ---------------------------------------------------------------------------
// Kernel 3: softmax over s for each b (32 blocks)
// ---------------------------------------------------------------------------
__global__ void softmax_kernel(const float* __restrict__ e,
                               float* __restrict__ beta) {
    __shared__ float red[256];
    int b = blockIdx.x;
    int tid = threadIdx.x;
    const float* eb = e + (size_t)b * SEQ;

    float m = -1e30f;
    for (int i = tid; i < SEQ; i += 256) m = fmaxf(m, eb[i]);
    red[tid] = m;
    __syncthreads();
    for (int s = 128; s > 0; s >>= 1) {
        if (tid < s) red[tid] = fmaxf(red[tid], red[tid + s]);
        __syncthreads();
    }
    m = red[0];
    __syncthreads();

    float sum = 0.0f;
    for (int i = tid; i < SEQ; i += 256) sum += expf(eb[i] - m);
    red[tid] = sum;
    __syncthreads();
    for (int s = 128; s > 0; s >>= 1) {
        if (tid < s) red[tid] += red[tid + s];
        __syncthreads();
    }
    float inv = 1.0f / red[0];

    for (int i = tid; i < SEQ; i += 256)
        beta[(size_t)b * SEQ + i] = expf(eb[i] - m) * inv;
}

// ---------------------------------------------------------------------------
// Kernel 4: out[b,v] = sum_s beta[b,s]*V[b,s,v]; s split across 8 CTAs per b.
// ---------------------------------------------------------------------------
#define SCHUNK 256
__global__ void out_kernel(const float* __restrict__ V,
                           const float* __restrict__ beta,
                           float* __restrict__ out) {
    __shared__ float bs[SCHUNK];
    int b  = blockIdx.y;
    int sc = blockIdx.x;               // 8 chunks of 256
    int tid = threadIdx.x;             // 256 threads, 4 v each (float4)

    bs[tid] = beta[(size_t)b * SEQ + sc * SCHUNK + tid];
    __syncthreads();

    const float4* Vp = (const float4*)(V + (size_t)b * SEQ * VLEN
                                         + (size_t)sc * SCHUNK * VLEN) + tid;
    float4 acc = make_float4(0.f, 0.f, 0.f, 0.f);
#pragma unroll 4
    for (int s = 0; s < SCHUNK; s++) {
        float4 v = Vp[(size_t)s * (VLEN / 4)];
        float w = bs[s];
        acc.x = fmaf(w, v.x, acc.x);
        acc.y = fmaf(w, v.y, acc.y);
        acc.z = fmaf(w, v.z, acc.z);
        acc.w = fmaf(w, v.w, acc.w);
    }
    float* o = out + (size_t)b * VLEN + tid * 4;
    atomicAdd(o + 0, acc.x);
    atomicAdd(o + 1, acc.y);
    atomicAdd(o + 2, acc.z);
    atomicAdd(o + 3, acc.w);
}

// ---------------------------------------------------------------------------
extern "C" void kernel_launch(void* const* d_in, const int* in_sizes, int n_in,
                              void* d_out, int out_size) {
    const float* h   = (const float*)d_in[0];
    const float* V   = (const float*)d_in[1];
    const float* Ww  = (const float*)d_in[2];
    const float* Wb  = (const float*)d_in[3];
    const float* Uw  = (const float*)d_in[4];
    const float* ww  = (const float*)d_in[5];
    float* out = (float*)d_out;

    float* e; float* beta; float* hproj;
    cudaGetSymbolAddress((void**)&e, g_e);
    cudaGetSymbolAddress((void**)&beta, g_beta);
    cudaGetSymbolAddress((void**)&hproj, g_hproj);

    zero_kernel<<<(MROWS + 255) / 256, 256>>>(e, out);
    hproj_kernel<<<(HID * 32 + 255) / 256, 256>>>(h, Ww, Wb, hproj);
    {
        dim3 grid(HID / BN, MROWS / BM);   // (8, 512)
        gemm_tanh_e_kernel<<<grid, 256>>>(V, Uw, hproj, ww, e);
    }
    softmax_kernel<<<BATCH, 256>>>(e, beta);
    {
        dim3 grid(SEQ / SCHUNK, BATCH);    // (8, 32)
        out_kernel<<<grid, SCHUNK>>>(V, beta, out);
    }
}